// round 3
// baseline (speedup 1.0000x reference)
#include <cuda_runtime.h>

#define EPSF     1e-9f
#define BCE_EPSF 1e-7f
#define NGT      150
#define NGT_PAD  152
#define NBLOCKS  1008   // 768 (s) + 192 (m) + 48 (l) with 256 threads/block

__device__ float g_part[NBLOCKS];

__global__ void __launch_bounds__(256) fused_loss_kernel(
    const float* __restrict__ s_out, const float* __restrict__ m_out,
    const float* __restrict__ l_out,
    const float* __restrict__ s_gt,  const float* __restrict__ m_gt,
    const float* __restrict__ l_gt,
    const float* __restrict__ s_gc,  const float* __restrict__ m_gc,
    const float* __restrict__ l_gc)
{
    __shared__ float4 s_box[NGT_PAD];   // tlx, tly, brx, bry
    __shared__ float  s_a2e3[NGT_PAD];  // (area2 + eps) / 3  (sentinel +3e38 on pad)
    __shared__ float  s_red[8];

    // ---- map block -> (scale, batch, local block) ----
    const int bb = blockIdx.x;
    const float *out_t, *gt_t, *gc;
    int b, lb, apb;
    if (bb < 768) {             // s: 48 blocks/batch, 12288 anchors
        b = bb / 48; lb = bb - b * 48; apb = 12288;
        out_t = s_out; gt_t = s_gt; gc = s_gc;
    } else if (bb < 960) {      // m: 12 blocks/batch, 3072 anchors
        int r = bb - 768; b = r / 12; lb = r - b * 12; apb = 3072;
        out_t = m_out; gt_t = m_gt; gc = m_gc;
    } else {                    // l: 3 blocks/batch, 768 anchors
        int r = bb - 960; b = r / 3; lb = r - b * 3; apb = 768;
        out_t = l_out; gt_t = l_gt; gc = l_gc;
    }

    // ---- stage gt boxes for this batch ----
    gc += (size_t)b * NGT * 4;
    for (int n = threadIdx.x; n < NGT_PAD; n += blockDim.x) {
        if (n < NGT) {
            float x = gc[n * 4 + 0], y = gc[n * 4 + 1];
            float w = gc[n * 4 + 2], h = gc[n * 4 + 3];
            float hw = 0.5f * w, hh = 0.5f * h;
            s_box[n]  = make_float4(x - hw, y - hh, x + hw, y + hh);
            s_a2e3[n] = (w * h + EPSF) * (1.0f / 3.0f);
        } else {
            s_box[n]  = make_float4(0.0f, 0.0f, 0.0f, 0.0f);
            s_a2e3[n] = 3.0e38f;   // sentinel: contribution = -inf
        }
    }
    __syncthreads();

    const int a = lb * blockDim.x + threadIdx.x;          // always < apb
    const size_t base = ((size_t)b * apb + a) * 5;
    const float* p = out_t + base;
    const float* q = gt_t  + base;
    float ox = p[0], oy = p[1], ow = p[2], oh = p[3], oc = p[4];
    float gx = q[0], gy = q[1], gw = q[2], gh = q[3], gcf = q[4];

    float tl1x = ox - 0.5f * ow, tl1y = oy - 0.5f * oh;
    float br1x = ox + 0.5f * ow, br1y = oy + 0.5f * oh;
    float area1 = ow * oh;

    // ---- DIoU vs paired gt ----
    float tl2x = gx - 0.5f * gw, tl2y = gy - 0.5f * gh;
    float br2x = gx + 0.5f * gw, br2y = gy + 0.5f * gh;
    float area2 = gw * gh;

    float iwx = fmaxf(fminf(br1x, br2x) - fmaxf(tl1x, tl2x), 0.0f);
    float iwy = fmaxf(fminf(br1y, br2y) - fmaxf(tl1y, tl2y), 0.0f);
    float inter = iwx * iwy;
    float iou = inter / (area1 + area2 - inter + EPSF);

    float dx = ox - gx, dy = oy - gy;
    float cd2 = dx * dx + dy * dy;
    float ex = fmaxf(br1x, br2x) - fminf(tl1x, tl2x);
    float ey = fmaxf(br1y, br2y) - fminf(tl1y, tl2y);
    float diou = iou - cd2 / (ex * ex + ey * ey + EPSF);

    float giou_loss = gcf * (2.0f - area2 * (1.0f / (512.0f * 512.0f))) * (1.0f - diou);

    // ---- background gate: any(iou vs gt_coords >= 0.5)?
    // iou >= 0.5 <=> inter - (area2+eps)/3 >= area1/3
    float m0 = -3.0e38f, m1 = -3.0e38f, m2 = -3.0e38f, m3 = -3.0e38f;
    #pragma unroll 2
    for (int n = 0; n < NGT_PAD; n += 4) {
        float4 b0 = s_box[n];
        float wx0 = fmaxf(fminf(br1x, b0.z) - fmaxf(tl1x, b0.x), 0.0f);
        float wy0 = fmaxf(fminf(br1y, b0.w) - fmaxf(tl1y, b0.y), 0.0f);
        m0 = fmaxf(m0, fmaf(wx0, wy0, -s_a2e3[n]));

        float4 b1 = s_box[n + 1];
        float wx1 = fmaxf(fminf(br1x, b1.z) - fmaxf(tl1x, b1.x), 0.0f);
        float wy1 = fmaxf(fminf(br1y, b1.w) - fmaxf(tl1y, b1.y), 0.0f);
        m1 = fmaxf(m1, fmaf(wx1, wy1, -s_a2e3[n + 1]));

        float4 b2 = s_box[n + 2];
        float wx2 = fmaxf(fminf(br1x, b2.z) - fmaxf(tl1x, b2.x), 0.0f);
        float wy2 = fmaxf(fminf(br1y, b2.w) - fmaxf(tl1y, b2.y), 0.0f);
        m2 = fmaxf(m2, fmaf(wx2, wy2, -s_a2e3[n + 2]));

        float4 b3 = s_box[n + 3];
        float wx3 = fmaxf(fminf(br1x, b3.z) - fmaxf(tl1x, b3.x), 0.0f);
        float wy3 = fmaxf(fminf(br1y, b3.w) - fmaxf(tl1y, b3.y), 0.0f);
        m3 = fmaxf(m3, fmaf(wx3, wy3, -s_a2e3[n + 3]));
    }
    float mall = fmaxf(fmaxf(m0, m1), fmaxf(m2, m3));
    float background = (mall >= area1 * (1.0f / 3.0f)) ? 0.0f : (1.0f - gcf);

    // ---- focal BCE conf loss ----
    float pcl = fminf(fmaxf(oc, BCE_EPSF), 1.0f - BCE_EPSF);
    float bce = -(gcf * __logf(pcl) + (1.0f - gcf) * __logf(1.0f - pcl));
    float d = gcf - oc;
    float focal = fabsf(gcf - 0.75f) * (d * d);
    float conf_loss = focal * (gcf + background) * bce;

    float loss = giou_loss + conf_loss;

    // ---- block reduction -> per-block partial ----
    #pragma unroll
    for (int off = 16; off > 0; off >>= 1)
        loss += __shfl_down_sync(0xffffffffu, loss, off);

    int wid = threadIdx.x >> 5, lid = threadIdx.x & 31;
    if (lid == 0) s_red[wid] = loss;
    __syncthreads();
    if (threadIdx.x == 0) {
        float t = 0.0f;
        #pragma unroll
        for (int i = 0; i < 8; i++) t += s_red[i];
        g_part[bb] = t;
    }
}

__global__ void __launch_bounds__(256) finalize_kernel(float* out, float inv_b) {
    __shared__ float s_red[8];
    double t = 0.0;
    for (int i = threadIdx.x; i < NBLOCKS; i += 256)
        t += (double)g_part[i];
    // warp reduce in double via float pairs: keep it simple with float after warp sums
    float f = (float)t;
    #pragma unroll
    for (int off = 16; off > 0; off >>= 1)
        f += __shfl_down_sync(0xffffffffu, f, off);
    int wid = threadIdx.x >> 5, lid = threadIdx.x & 31;
    if (lid == 0) s_red[wid] = f;
    __syncthreads();
    if (threadIdx.x == 0) {
        float s = 0.0f;
        #pragma unroll
        for (int i = 0; i < 8; i++) s += s_red[i];
        out[0] = s * inv_b;
    }
}

extern "C" void kernel_launch(void* const* d_in, const int* in_sizes, int n_in,
                              void* d_out, int out_size)
{
    const float* s_out = (const float*)d_in[0];
    const float* m_out = (const float*)d_in[1];
    const float* l_out = (const float*)d_in[2];
    const float* s_gt  = (const float*)d_in[3];
    const float* m_gt  = (const float*)d_in[4];
    const float* l_gt  = (const float*)d_in[5];
    const float* s_gc  = (const float*)d_in[6];
    const float* m_gc  = (const float*)d_in[7];
    const float* l_gc  = (const float*)d_in[8];

    const int B = in_sizes[6] / (NGT * 4);   // 16

    fused_loss_kernel<<<NBLOCKS, 256>>>(s_out, m_out, l_out,
                                        s_gt, m_gt, l_gt,
                                        s_gc, m_gc, l_gc);
    finalize_kernel<<<1, 256>>>((float*)d_out, 1.0f / (float)B);
}

// round 4
// speedup vs baseline: 1.1889x; 1.1889x over previous
#include <cuda_runtime.h>

#define EPSF     1e-9f
#define BCE_EPSF 1e-7f
#define NGT      150
#define NGT_PAD  152
#define NBLOCKS  1008   // 768 (s) + 192 (m) + 48 (l) with 256 threads/block

__device__ double       g_acc;     // zero-initialized at module load; reset by last block
__device__ unsigned int g_count;   // arrival counter, reset by last block

__global__ void __launch_bounds__(256) fused_loss_kernel(
    const float* __restrict__ s_out, const float* __restrict__ m_out,
    const float* __restrict__ l_out,
    const float* __restrict__ s_gt,  const float* __restrict__ m_gt,
    const float* __restrict__ l_gt,
    const float* __restrict__ s_gc,  const float* __restrict__ m_gc,
    const float* __restrict__ l_gc,
    float* __restrict__ out, float inv_b)
{
    __shared__ float4 s_box[NGT_PAD];        // tlx, tly, brx, bry
    __shared__ float4 s_a43[NGT_PAD / 4];    // -(area2+eps)/3, 4 boxes per float4
    __shared__ float  s_red[8];

    // ---- map block -> (scale, batch, local block) ----
    const int bb = blockIdx.x;
    const float *out_t, *gt_t, *gc;
    int b, lb, apb;
    if (bb < 768) {             // s: 48 blocks/batch, 12288 anchors
        b = bb / 48; lb = bb - b * 48; apb = 12288;
        out_t = s_out; gt_t = s_gt; gc = s_gc;
    } else if (bb < 960) {      // m: 12 blocks/batch, 3072 anchors
        int r = bb - 768; b = r / 12; lb = r - b * 12; apb = 3072;
        out_t = m_out; gt_t = m_gt; gc = m_gc;
    } else {                    // l: 3 blocks/batch, 768 anchors
        int r = bb - 960; b = r / 3; lb = r - b * 3; apb = 768;
        out_t = l_out; gt_t = l_gt; gc = l_gc;
    }

    // ---- stage gt boxes for this batch ----
    gc += (size_t)b * NGT * 4;
    for (int n = threadIdx.x; n < NGT_PAD; n += blockDim.x) {
        float th;
        if (n < NGT) {
            float x = gc[n * 4 + 0], y = gc[n * 4 + 1];
            float w = gc[n * 4 + 2], h = gc[n * 4 + 3];
            float hw = 0.5f * w, hh = 0.5f * h;
            s_box[n] = make_float4(x - hw, y - hh, x + hw, y + hh);
            th = -(w * h + EPSF) * (1.0f / 3.0f);
        } else {
            s_box[n] = make_float4(0.0f, 0.0f, 0.0f, 0.0f);
            th = -3.0e38f;          // sentinel: contribution = -inf
        }
        ((float*)s_a43)[n] = th;
    }
    __syncthreads();

    const int a = lb * blockDim.x + threadIdx.x;          // always < apb
    const size_t base = ((size_t)b * apb + a) * 5;
    const float* p = out_t + base;
    const float* q = gt_t  + base;
    float ox = p[0], oy = p[1], ow = p[2], oh = p[3], oc = p[4];
    float gx = q[0], gy = q[1], gw = q[2], gh = q[3], gcf = q[4];

    float tl1x = ox - 0.5f * ow, tl1y = oy - 0.5f * oh;
    float br1x = ox + 0.5f * ow, br1y = oy + 0.5f * oh;
    float area1 = ow * oh;

    // ---- DIoU vs paired gt ----
    float tl2x = gx - 0.5f * gw, tl2y = gy - 0.5f * gh;
    float br2x = gx + 0.5f * gw, br2y = gy + 0.5f * gh;
    float area2 = gw * gh;

    float iwx = fmaxf(fminf(br1x, br2x) - fmaxf(tl1x, tl2x), 0.0f);
    float iwy = fmaxf(fminf(br1y, br2y) - fmaxf(tl1y, tl2y), 0.0f);
    float inter = iwx * iwy;
    float iou = inter / (area1 + area2 - inter + EPSF);

    float dx = ox - gx, dy = oy - gy;
    float cd2 = dx * dx + dy * dy;
    float ex = fmaxf(br1x, br2x) - fminf(tl1x, tl2x);
    float ey = fmaxf(br1y, br2y) - fminf(tl1y, tl2y);
    float diou = iou - cd2 / (ex * ex + ey * ey + EPSF);

    float giou_loss = gcf * (2.0f - area2 * (1.0f / (512.0f * 512.0f))) * (1.0f - diou);

    // ---- background gate: any(iou vs gt_coords >= 0.5)?
    // iou >= 0.5 <=> inter >= (area1 + area2 + eps)/3
    // gate with single clamp: max(wx,0)*wy  (<=0 whenever true inter would be 0)
    float m0 = -3.0e38f, m1 = -3.0e38f, m2 = -3.0e38f, m3 = -3.0e38f;
    #pragma unroll 2
    for (int n = 0; n < NGT_PAD; n += 4) {
        float4 th = s_a43[n >> 2];   // pre-negated thresholds for boxes n..n+3

        float4 b0 = s_box[n];
        float wx0 = fminf(br1x, b0.z) - fmaxf(tl1x, b0.x);
        float wy0 = fminf(br1y, b0.w) - fmaxf(tl1y, b0.y);
        m0 = fmaxf(m0, fmaf(fmaxf(wx0, 0.0f), wy0, th.x));

        float4 b1 = s_box[n + 1];
        float wx1 = fminf(br1x, b1.z) - fmaxf(tl1x, b1.x);
        float wy1 = fminf(br1y, b1.w) - fmaxf(tl1y, b1.y);
        m1 = fmaxf(m1, fmaf(fmaxf(wx1, 0.0f), wy1, th.y));

        float4 b2 = s_box[n + 2];
        float wx2 = fminf(br1x, b2.z) - fmaxf(tl1x, b2.x);
        float wy2 = fminf(br1y, b2.w) - fmaxf(tl1y, b2.y);
        m2 = fmaxf(m2, fmaf(fmaxf(wx2, 0.0f), wy2, th.z));

        float4 b3 = s_box[n + 3];
        float wx3 = fminf(br1x, b3.z) - fmaxf(tl1x, b3.x);
        float wy3 = fminf(br1y, b3.w) - fmaxf(tl1y, b3.y);
        m3 = fmaxf(m3, fmaf(fmaxf(wx3, 0.0f), wy3, th.w));
    }
    float mall = fmaxf(fmaxf(m0, m1), fmaxf(m2, m3));
    float background = (mall >= area1 * (1.0f / 3.0f)) ? 0.0f : (1.0f - gcf);

    // ---- focal BCE conf loss ----
    float pcl = fminf(fmaxf(oc, BCE_EPSF), 1.0f - BCE_EPSF);
    float bce = -(gcf * __logf(pcl) + (1.0f - gcf) * __logf(1.0f - pcl));
    float d = gcf - oc;
    float focal = fabsf(gcf - 0.75f) * (d * d);
    float conf_loss = focal * (gcf + background) * bce;

    float loss = giou_loss + conf_loss;

    // ---- block reduction ----
    #pragma unroll
    for (int off = 16; off > 0; off >>= 1)
        loss += __shfl_down_sync(0xffffffffu, loss, off);

    int wid = threadIdx.x >> 5, lid = threadIdx.x & 31;
    if (lid == 0) s_red[wid] = loss;
    __syncthreads();

    // ---- global accumulate; last block writes output and resets state ----
    if (threadIdx.x == 0) {
        float t = 0.0f;
        #pragma unroll
        for (int i = 0; i < 8; i++) t += s_red[i];
        atomicAdd(&g_acc, (double)t);
        __threadfence();
        unsigned int old = atomicAdd(&g_count, 1u);
        if (old == NBLOCKS - 1) {
            double v = atomicAdd(&g_acc, 0.0);   // atomic read (L2-coherent)
            out[0] = (float)(v * (double)inv_b);
            g_acc = 0.0;                          // reset for next graph replay
            g_count = 0u;
            __threadfence();
        }
    }
}

extern "C" void kernel_launch(void* const* d_in, const int* in_sizes, int n_in,
                              void* d_out, int out_size)
{
    const float* s_out = (const float*)d_in[0];
    const float* m_out = (const float*)d_in[1];
    const float* l_out = (const float*)d_in[2];
    const float* s_gt  = (const float*)d_in[3];
    const float* m_gt  = (const float*)d_in[4];
    const float* l_gt  = (const float*)d_in[5];
    const float* s_gc  = (const float*)d_in[6];
    const float* m_gc  = (const float*)d_in[7];
    const float* l_gc  = (const float*)d_in[8];

    const int B = in_sizes[6] / (NGT * 4);   // 16

    fused_loss_kernel<<<NBLOCKS, 256>>>(s_out, m_out, l_out,
                                        s_gt, m_gt, l_gt,
                                        s_gc, m_gc, l_gc,
                                        (float*)d_out, 1.0f / (float)B);
}